// round 15
// baseline (speedup 1.0000x reference)
#include <cuda_runtime.h>
#include <cuda_bf16.h>
#include <math.h>
#include <float.h>
#include <stdint.h>

#define NB 2048
#define ND 256
#define NS 64
#define NK 1024
#define TD 512          // 2*D
#define SD (NS*ND)      // 16384
#define KX 1536         // 3*TD for bf16x3
#define BETA 0.25f

// ---------------- device scratch ----------------
__device__ float g_mr[(size_t)NB*SD];
__device__ float g_mi[(size_t)NB*SD];
__device__ float g_gr[NB*ND];
__device__ float g_gi[NB*ND];
__device__ float g_zf[(size_t)NB*TD];
__device__ __nv_bfloat16 g_zb[(size_t)NB*KX];   // [zh | zh | zm]
__device__ __nv_bfloat16 g_cbb[(size_t)NK*KX];  // [ch | cm | ch]
__device__ float g_eff[NB*NS];
__device__ float g_ysq[NK];
__device__ float g_alog[NK*65];
__device__ float g_blog[NB*65];
__device__ float g_plog[4*NB*65];
__device__ float g_pscore[NB*16];
__device__ int   g_pidx[NB*16];
__device__ int   g_hist[5*NK];
__device__ float g_aux;

// ---------------- helpers ----------------
__device__ __forceinline__ float warp_sum(float v){
    #pragma unroll
    for(int o=16;o;o>>=1) v += __shfl_xor_sync(0xffffffffu, v, o);
    return v;
}
__device__ __forceinline__ void warp_sum2(float& a, float& b){
    #pragma unroll
    for(int o=16;o;o>>=1){
        a += __shfl_xor_sync(0xffffffffu, a, o);
        b += __shfl_xor_sync(0xffffffffu, b, o);
    }
}
__device__ __forceinline__ float warp_max(float v){
    #pragma unroll
    for(int o=16;o;o>>=1) v = fmaxf(v, __shfl_xor_sync(0xffffffffu, v, o));
    return v;
}
__device__ __forceinline__ float dot4(float4 a, float4 b){
    return a.x*b.x + a.y*b.y + a.z*b.z + a.w*b.w;
}
__device__ __forceinline__ void fma4(float4& acc, float s, float4 v){
    acc.x += s*v.x; acc.y += s*v.y; acc.z += s*v.z; acc.w += s*v.w;
}
__device__ __forceinline__ void scl4(float4& acc, float s){
    acc.x *= s; acc.y *= s; acc.z *= s; acc.w *= s;
}
__device__ __forceinline__ float4 mix4(float om, float4 a, float e, float4 g){
    float4 r; r.x=om*a.x+e*g.x; r.y=om*a.y+e*g.y; r.z=om*a.z+e*g.z; r.w=om*a.w+e*g.w; return r;
}
__device__ __forceinline__ float h4(float4 v){ return v.x+v.y+v.z+v.w; }
__device__ __forceinline__ float ss4(float4 v){
    return v.x*v.x + v.y*v.y + v.z*v.z + v.w*v.w;
}
__device__ __forceinline__ float4 lnorm4(float4 v, float mu, float inv, float4 w, float4 b){
    float4 r;
    r.x=(v.x-mu)*inv*w.x+b.x; r.y=(v.y-mu)*inv*w.y+b.y;
    r.z=(v.z-mu)*inv*w.z+b.z; r.w=(v.w-mu)*inv*w.w+b.w; return r;
}
__device__ __forceinline__ float4 zero4(){ float4 z; z.x=z.y=z.z=z.w=0.f; return z; }
__device__ __forceinline__ void cp16(void* dst, const void* src){
    unsigned u = (unsigned)__cvta_generic_to_shared(dst);
    asm volatile("cp.async.cg.shared.global [%0], [%1], 16;" :: "r"(u), "l"(src));
}
__device__ __forceinline__ void mma16(float* d, const unsigned* a, const unsigned* b){
    asm volatile("mma.sync.aligned.m16n8k16.row.col.f32.bf16.bf16.f32 "
        "{%0,%1,%2,%3},{%4,%5,%6,%7},{%8,%9},{%0,%1,%2,%3};"
        : "+f"(d[0]),"+f"(d[1]),"+f"(d[2]),"+f"(d[3])
        : "r"(a[0]),"r"(a[1]),"r"(a[2]),"r"(a[3]),"r"(b[0]),"r"(b[1]));
}

// ---------------- softmax/top3/eff (warp-collective, returns lane-partial ent)
__device__ __forceinline__ float addr_finish(int b, float v0, float v1, float gate, int lane){
    float m  = warp_max(fmaxf(v0,v1));
    float e0 = expf(v0-m), e1 = expf(v1-m);
    float ssum = warp_sum(e0+e1);
    float w0 = e0/ssum, w1 = e1/ssum;
    float ent = -(w0*logf(w0+1e-10f)) - (w1*logf(w1+1e-10f));
    float a0=w0, a1=w1; int i0=lane, i1=lane+32;
    float tv[3]; int ti[3];
    #pragma unroll
    for(int p3=0;p3<3;p3++){
        float v; int ix;
        if(a0>a1 || (a0==a1 && i0<i1)){ v=a0; ix=i0; } else { v=a1; ix=i1; }
        #pragma unroll
        for(int o=16;o;o>>=1){
            float ov = __shfl_xor_sync(0xffffffffu, v, o);
            int   oi = __shfl_xor_sync(0xffffffffu, ix, o);
            if(ov>v || (ov==v && oi<ix)){ v=ov; ix=oi; }
        }
        tv[p3]=v; ti[p3]=ix;
        if(i0==ix) a0 = -1.f;
        if(i1==ix) a1 = -1.f;
    }
    float norm = 1.f/(tv[0]+tv[1]+tv[2]+1e-6f);
    float o0=0.f, o1=0.f;
    #pragma unroll
    for(int p3=0;p3<3;p3++){
        if(lane==ti[p3])    o0 = tv[p3]*norm;
        if(lane+32==ti[p3]) o1 = tv[p3]*norm;
    }
    g_eff[b*NS+lane]    = gate*o0;
    g_eff[b*NS+lane+32] = gate*o1;
    return ent;
}

// ---------------- init: ysq, codebook bf16x3 split, zero hist/aux ------------
__global__ void k_init(const float* __restrict__ cb){
    int gt = blockIdx.x*256 + threadIdx.x;
    int w = gt >> 5, lane = gt & 31;
    const float* row = cb + (size_t)w*TD;
    float p = 0.f;
    for(int j=lane;j<TD;j+=32){
        float c = row[j];
        p += c*c;
        __nv_bfloat16 ch = __float2bfloat16_rn(c);
        __nv_bfloat16 cm = __float2bfloat16_rn(c - __bfloat162float(ch));
        size_t base = (size_t)w*KX;
        g_cbb[base + j]        = ch;
        g_cbb[base + 512 + j]  = cm;
        g_cbb[base + 1024 + j] = ch;
    }
    p = warp_sum(p);
    if(lane==0) g_ysq[w] = p;
    if(gt < 5*NK) g_hist[gt] = 0;
    if(gt == 0) g_aux = 0.f;
}

// ---------------- logits GEMM (split-K x4) ----------------------------------
__global__ void __launch_bounds__(256) k_logits(int mode, const float* __restrict__ cb,
                                                const float* __restrict__ gr_in,
                                                const float* __restrict__ gi_in,
                                                const float* __restrict__ aw,
                                                const float* __restrict__ gw){
    __shared__ float s_w[65*68];
    __shared__ float s_x[32*68];
    int t = threadIdx.x;
    int ml = t >> 3, ng = t & 7;
    int m0 = blockIdx.x*32;
    int kb = blockIdx.y*128;
    float acc[9];
    #pragma unroll
    for(int i=0;i<9;i++) acc[i]=0.f;

    #pragma unroll
    for(int ch=0; ch<2; ch++){
        int k0 = kb + ch*64;
        __syncthreads();
        for(int idx=t; idx<1040; idx+=256){
            int n = idx>>4, j4 = (idx&15)*4;
            float4 v = (n<64) ? *(const float4*)&aw[(size_t)n*TD + k0 + j4]
                              : *(const float4*)&gw[k0 + j4];
            *(float4*)&s_w[n*68+j4] = v;
        }
        #pragma unroll
        for(int l=0;l<2;l++){
            int idx = t + l*256;
            int mm = idx>>4, j4 = (idx&15)*4;
            int kg = k0 + j4;
            const float* src;
            if(mode) src = &cb[(size_t)(m0+mm)*TD + kg];
            else     src = (kg < 256) ? &gr_in[(m0+mm)*ND + kg] : &gi_in[(m0+mm)*ND + kg - 256];
            *(float4*)&s_x[mm*68+j4] = *(const float4*)src;
        }
        __syncthreads();
        #pragma unroll 4
        for(int j=0;j<64;j+=4){
            float4 xv = *(const float4*)&s_x[ml*68+j];
            #pragma unroll
            for(int i=0;i<8;i++){
                float4 wv = *(const float4*)&s_w[(ng+i*8)*68+j];
                acc[i] += dot4(xv, wv);
            }
            if(ng==0){
                float4 wv = *(const float4*)&s_w[64*68+j];
                acc[8] += dot4(xv, wv);
            }
        }
    }
    float* pp = g_plog + blockIdx.y*(NB*65);
    int m = m0 + ml;
    #pragma unroll
    for(int i=0;i<8;i++) pp[m*65 + ng + i*8] = acc[i];
    if(ng==0) pp[m*65 + 64] = acc[8];
}

// ---------------- logits reduce ----------------------------------------------
__global__ void k_logred(int mode, const float* __restrict__ ab, const float* __restrict__ gb){
    int idx = blockIdx.x*256 + threadIdx.x;
    int M = mode ? NK : NB;
    if(idx >= M*65) return;
    int n = idx - (idx/65)*65;
    float s = g_plog[idx] + g_plog[NB*65+idx] + g_plog[2*NB*65+idx] + g_plog[3*NB*65+idx];
    s += (n < 64) ? ab[n] : gb[0];
    if(mode) g_alog[idx] = s; else g_blog[idx] = s;
}

// ---------------- iter-0 address finisher ------------------------------------
__global__ void __launch_bounds__(256) k_addr_fin(){
    int t = threadIdx.x, wid = t>>5, lane = t&31;
    int b = blockIdx.x*8 + wid;
    const float* row = g_blog + b*65;
    float gate = 1.f/(1.f + expf(-row[64]));
    float ent = warp_sum(addr_finish(b, row[lane], row[lane+32], gate, lane));
    __shared__ float s_e[8];
    if(lane==0) s_e[wid] = ent;
    __syncthreads();
    if(t==0){
        float es = 0.f;
        #pragma unroll
        for(int i=0;i<8;i++) es += s_e[i];
        atomicAdd(&g_aux, es*(1.f/(float)NB));
    }
}

// ---- fused assoc-mem (single pass, online softmax) + complex layernorm ------
__global__ void __launch_bounds__(512,4) k_mem(const float* __restrict__ mr_in,
                                               const float* __restrict__ mi_in,
                                               const float* __restrict__ gr_in,
                                               const float* __restrict__ gi_in,
                                               int first, int last,
                                               const float* __restrict__ lnrw, const float* __restrict__ lnrb,
                                               const float* __restrict__ lniw, const float* __restrict__ lnib,
                                               const float* __restrict__ clns, const float* __restrict__ clnb)
{
    __shared__ float s_g[TD];
    __shared__ float s_eff[NS];
    __shared__ float s_part[16*TD];
    __shared__ float s_wm[16];
    __shared__ float s_ws[16];
    __shared__ float s_wscale[17];
    __shared__ float s_red2[16];
    __shared__ float s_scal[2];

    int b = blockIdx.x, t = threadIdx.x, wid = t>>5, lane = t&31;
    const float* mrs = first ? (mr_in + (size_t)b*SD) : (g_mr + (size_t)b*SD);
    const float* mis = first ? (mi_in + (size_t)b*SD) : (g_mi + (size_t)b*SD);

    if(t<ND) s_g[t] = first ? gr_in[b*ND+t] : g_gr[b*ND+t];
    else     s_g[t] = first ? gi_in[b*ND + (t-ND)] : g_gi[b*ND + (t-ND)];
    if(t<NS) s_eff[t] = g_eff[b*NS+t];
    __syncthreads();

    const float4* sg4 = (const float4*)s_g;   // g stays in smem (register budget)

    float4 ar0=zero4(), ar1=zero4(), ai0=zero4(), ai1=zero4();
    float om_m = -FLT_MAX, om_s = 0.f;

    int s0 = wid*4;
    float4 A0, A1, C0, C1, P0, P1, P2, P3;
    {
        const float4* pr = (const float4*)(mrs + s0*ND);
        const float4* pi = (const float4*)(mis + s0*ND);
        A0 = __ldcs(&pr[lane]); A1 = __ldcs(&pr[lane+32]);
        C0 = __ldcs(&pi[lane]); C1 = __ldcs(&pi[lane+32]);
    }

    #pragma unroll
    for(int r=0;r<4;r++){
        int s = s0 + r;
        if(r < 3){
            const float4* pr = (const float4*)(mrs + (s+1)*ND);
            const float4* pi = (const float4*)(mis + (s+1)*ND);
            P0 = __ldcs(&pr[lane]); P1 = __ldcs(&pr[lane+32]);
            P2 = __ldcs(&pi[lane]); P3 = __ldcs(&pi[lane+32]);
        }

        float sim = warp_sum(dot4(A0,sg4[lane]) + dot4(A1,sg4[lane+32])
                           + dot4(C0,sg4[64+lane]) + dot4(C1,sg4[64+lane+32]));

        float mnew = fmaxf(om_m, sim);
        float scale = expf(om_m - mnew);
        float w = expf(sim - mnew);
        scl4(ar0, scale); scl4(ar1, scale); scl4(ai0, scale); scl4(ai1, scale);
        fma4(ar0, w, A0); fma4(ar1, w, A1);
        fma4(ai0, w, C0); fma4(ai1, w, C1);
        om_s = om_s*scale + w;
        om_m = mnew;

        if(!last){
            float e = s_eff[s], om = 1.f - e;
            {
                float4 v0 = mix4(om, A0, e, sg4[lane]), v1 = mix4(om, A1, e, sg4[lane+32]);
                float sv = h4(v0)+h4(v1), sq = ss4(v0)+ss4(v1);
                warp_sum2(sv, sq);
                float mu  = sv*(1.f/ND);
                float var = sq*(1.f/ND) - mu*mu;
                float inv = 1.f/sqrtf(var + 1e-6f);
                const float4* w4 = (const float4*)lnrw; const float4* b4 = (const float4*)lnrb;
                float4* dst = (float4*)(g_mr + (size_t)b*SD + s*ND);
                __stcs(&dst[lane],    lnorm4(v0, mu, inv, __ldg(&w4[lane]),    __ldg(&b4[lane])));
                __stcs(&dst[lane+32], lnorm4(v1, mu, inv, __ldg(&w4[lane+32]), __ldg(&b4[lane+32])));
            }
            {
                float4 v0 = mix4(om, C0, e, sg4[64+lane]), v1 = mix4(om, C1, e, sg4[64+lane+32]);
                float sv = h4(v0)+h4(v1), sq = ss4(v0)+ss4(v1);
                warp_sum2(sv, sq);
                float mu  = sv*(1.f/ND);
                float var = sq*(1.f/ND) - mu*mu;
                float inv = 1.f/sqrtf(var + 1e-6f);
                const float4* w4 = (const float4*)lniw; const float4* b4 = (const float4*)lnib;
                float4* dst = (float4*)(g_mi + (size_t)b*SD + s*ND);
                __stcs(&dst[lane],    lnorm4(v0, mu, inv, __ldg(&w4[lane]),    __ldg(&b4[lane])));
                __stcs(&dst[lane+32], lnorm4(v1, mu, inv, __ldg(&w4[lane+32]), __ldg(&b4[lane+32])));
            }
        }
        A0 = P0; A1 = P1; C0 = P2; C1 = P3;
    }

    {
        float4* sp4 = (float4*)&s_part[wid*TD];
        sp4[lane]    = ar0; sp4[lane+32]    = ar1;
        sp4[64+lane] = ai0; sp4[64+lane+32] = ai1;
        if(lane==0){ s_wm[wid] = om_m; s_ws[wid] = om_s; }
    }
    __syncthreads();

    if(wid==0 && lane==0){
        float M = -FLT_MAX;
        #pragma unroll
        for(int w=0;w<16;w++) M = fmaxf(M, s_wm[w]);
        float total = 0.f;
        #pragma unroll
        for(int w=0;w<16;w++){
            float sc = expf(s_wm[w] - M);
            s_wscale[w] = sc;
            total += s_ws[w]*sc;
        }
        s_wscale[16] = 1.f/total;
    }
    __syncthreads();

    float invt = s_wscale[16];
    float red = 0.f;
    #pragma unroll
    for(int w=0;w<16;w++) red += s_wscale[w]*s_part[w*TD + t];
    red *= invt;
    __syncthreads();
    s_part[t] = red;
    __syncthreads();

    float zr=0.f, zi=0.f, mag=0.f;
    if(t < ND){
        zr = s_g[t]    + s_part[t];
        zi = s_g[ND+t] + s_part[ND+t];
        mag = sqrtf(zr*zr + zi*zi + 1e-8f);
    }
    float p = warp_sum(mag);
    if(lane==0) s_red2[wid] = p;
    __syncthreads();
    if(t==0){
        float m2=0.f;
        #pragma unroll
        for(int i=0;i<8;i++) m2 += s_red2[i];
        s_scal[0] = m2*(1.f/ND);
    }
    __syncthreads();
    float mean = s_scal[0];
    float dv = (t<ND) ? (mag-mean)*(mag-mean) : 0.f;
    p = warp_sum(dv);
    if(lane==0) s_red2[wid] = p;
    __syncthreads();
    if(t==0){
        float v2=0.f;
        #pragma unroll
        for(int i=0;i<8;i++) v2 += s_red2[i];
        s_scal[1] = 1.f/sqrtf(v2*(1.f/(ND-1)) + 1e-4f);
    }
    __syncthreads();
    if(t < ND){
        float nm = (mag-mean)*s_scal[1]*__ldg(&clns[t]) + __ldg(&clnb[t]);
        float h2 = zr*zr + zi*zi;
        float c, s;
        if(h2 > 0.f){ float ih = 1.f/sqrtf(h2); c = zr*ih; s = zi*ih; }
        else { c = 1.f; s = 0.f; }
        float zrv = nm*c, ziv = nm*s;
        size_t zfb = (size_t)b*TD;
        g_zf[zfb + t]      = zrv;
        g_zf[zfb + ND + t] = ziv;
        size_t zbb = (size_t)b*KX;
        __nv_bfloat16 hr = __float2bfloat16_rn(zrv);
        __nv_bfloat16 mr2 = __float2bfloat16_rn(zrv - __bfloat162float(hr));
        g_zb[zbb + t]         = hr;
        g_zb[zbb + 512 + t]   = hr;
        g_zb[zbb + 1024 + t]  = mr2;
        __nv_bfloat16 hi = __float2bfloat16_rn(ziv);
        __nv_bfloat16 mi2 = __float2bfloat16_rn(ziv - __bfloat162float(hi));
        g_zb[zbb + ND + t]        = hi;
        g_zb[zbb + 512 + ND + t]  = hi;
        g_zb[zbb + 1024 + ND + t] = mi2;
    }
}

// ---------------- VQ: bf16 HMMA distance GEMM + argmin ----------------------
#define VQ_A_BYTES 18432
#define VQ_B_BYTES 9216
#define VQ_STG (VQ_A_BYTES+VQ_B_BYTES)
__global__ void __launch_bounds__(256,2) k_vq(){
    extern __shared__ char vsm[];
    int tid = threadIdx.x, lane = tid&31, wid = tid>>5;
    int g = lane>>2, tig = lane&3;
    int wm = wid>>1, wn = wid&1;
    int b0 = blockIdx.x*128, k0 = blockIdx.y*64;

    float acc[2][4][4];
    #pragma unroll
    for(int i=0;i<2;i++)
        #pragma unroll
        for(int j=0;j<4;j++){ acc[i][j][0]=0.f; acc[i][j][1]=0.f; acc[i][j][2]=0.f; acc[i][j][3]=0.f; }

    #define LOAD_CHUNK(ch, stage) do{ \
        _Pragma("unroll") \
        for(int i=0;i<6;i++){ \
            int q = tid + i*256; \
            if(q < 1024){ \
                int row = q>>3, seg = q&7; \
                cp16(vsm + (stage)*VQ_STG + row*144 + seg*16, \
                     &g_zb[(size_t)(b0+row)*KX + (ch)*64 + seg*8]); \
            } else { \
                int q2 = q-1024; int row = q2>>3, seg = q2&7; \
                cp16(vsm + (stage)*VQ_STG + VQ_A_BYTES + row*144 + seg*16, \
                     &g_cbb[(size_t)(k0+row)*KX + (ch)*64 + seg*8]); \
            } \
        } \
        asm volatile("cp.async.commit_group;"); \
    }while(0)

    LOAD_CHUNK(0, 0);

    for(int ch=0; ch<24; ch++){
        if(ch < 23){
            LOAD_CHUNK(ch+1, (ch+1)&1);
            asm volatile("cp.async.wait_group 1;");
        } else {
            asm volatile("cp.async.wait_group 0;");
        }
        __syncthreads();

        const char* As = vsm + (ch&1)*VQ_STG;
        const char* Bs = As + VQ_A_BYTES;

        #pragma unroll
        for(int kk=0;kk<4;kk++){
            unsigned a[2][4], bfr[4][2];
            #pragma unroll
            for(int m4=0;m4<2;m4++){
                int r = wm*32 + m4*16 + g;
                const char* p = As + r*144 + kk*32 + tig*4;
                a[m4][0] = *(const unsigned*)p;
                a[m4][1] = *(const unsigned*)(p + 8*144);
                a[m4][2] = *(const unsigned*)(p + 16);
                a[m4][3] = *(const unsigned*)(p + 8*144 + 16);
            }
            #pragma unroll
            for(int n4=0;n4<4;n4++){
                int c = wn*32 + n4*8 + g;
                const char* p = Bs + c*144 + kk*32 + tig*4;
                bfr[n4][0] = *(const unsigned*)p;
                bfr[n4][1] = *(const unsigned*)(p + 16);
            }
            #pragma unroll
            for(int m4=0;m4<2;m4++)
                #pragma unroll
                for(int n4=0;n4<4;n4++)
                    mma16(acc[m4][n4], a[m4], bfr[n4]);
        }
        __syncthreads();
    }

    float* s_val = (float*)vsm;
    int*   s_idx = (int*)(vsm + 1024);

    float ys[4][2];
    #pragma unroll
    for(int n4=0;n4<4;n4++){
        int c = k0 + wn*32 + n4*8 + tig*2;
        ys[n4][0] = __ldg(&g_ysq[c]);
        ys[n4][1] = __ldg(&g_ysq[c+1]);
    }

    #pragma unroll
    for(int m4=0;m4<2;m4++){
        float bvA = FLT_MAX, bvB = FLT_MAX; int biA = 0x7fffffff, biB = 0x7fffffff;
        #pragma unroll
        for(int n4=0;n4<4;n4++){
            int cb0 = k0 + wn*32 + n4*8 + tig*2;
            float d0 = ys[n4][0] - 2.f*acc[m4][n4][0];
            float d1 = ys[n4][1] - 2.f*acc[m4][n4][1];
            float d2 = ys[n4][0] - 2.f*acc[m4][n4][2];
            float d3 = ys[n4][1] - 2.f*acc[m4][n4][3];
            if(d0 < bvA || (d0==bvA && cb0   < biA)){ bvA = d0; biA = cb0;   }
            if(d1 < bvA || (d1==bvA && cb0+1 < biA)){ bvA = d1; biA = cb0+1; }
            if(d2 < bvB || (d2==bvB && cb0   < biB)){ bvB = d2; biB = cb0;   }
            if(d3 < bvB || (d3==bvB && cb0+1 < biB)){ bvB = d3; biB = cb0+1; }
        }
        #pragma unroll
        for(int o=1;o<4;o<<=1){
            float ovA = __shfl_xor_sync(0xffffffffu, bvA, o);
            int   oiA = __shfl_xor_sync(0xffffffffu, biA, o);
            if(ovA<bvA || (ovA==bvA && oiA<biA)){ bvA=ovA; biA=oiA; }
            float ovB = __shfl_xor_sync(0xffffffffu, bvB, o);
            int   oiB = __shfl_xor_sync(0xffffffffu, biB, o);
            if(ovB<bvB || (ovB==bvB && oiB<biB)){ bvB=ovB; biB=oiB; }
        }
        if(tig==0){
            int rA = wm*32 + m4*16 + g;
            s_val[rA*2+wn]     = bvA; s_idx[rA*2+wn]     = biA;
            s_val[(rA+8)*2+wn] = bvB; s_idx[(rA+8)*2+wn] = biB;
        }
    }
    __syncthreads();
    if(tid < 128){
        float bv = FLT_MAX; int bi = 0x7fffffff;
        #pragma unroll
        for(int j=0;j<2;j++){
            float v = s_val[tid*2+j]; int ix = s_idx[tid*2+j];
            if(v<bv || (v==bv && ix<bi)){ bv=v; bi=ix; }
        }
        g_pscore[(size_t)(b0+tid)*16 + blockIdx.y] = bv;
        g_pidx  [(size_t)(b0+tid)*16 + blockIdx.y] = bi;
    }
    #undef LOAD_CHUNK
}

// ------- final argmin, gather, loss, hist + fused next-iter address ----------
__global__ void __launch_bounds__(256) k_pick(const float* __restrict__ cb, int it, int do_addr){
    int wid = threadIdx.x>>5, lane = threadIdx.x&31;
    int b = blockIdx.x*8 + wid;
    float bv = FLT_MAX; int bi = 0x7fffffff;
    if(lane < 16){ bv = g_pscore[b*16+lane]; bi = g_pidx[b*16+lane]; }
    #pragma unroll
    for(int o=1;o<32;o<<=1){
        float ov = __shfl_xor_sync(0xffffffffu, bv, o);
        int   oi = __shfl_xor_sync(0xffffffffu, bi, o);
        if(ov<bv || (ov==bv && oi<bi)){ bv=ov; bi=oi; }
    }
    bi = __shfl_sync(0xffffffffu, bi, 0);
    const float* row = cb + (size_t)bi*TD;
    float lacc = 0.f;
    for(int j=lane;j<TD;j+=32){
        float c = row[j], z = g_zf[(size_t)b*TD + j];
        float df = c - z; lacc += df*df;
        if(j < ND) g_gr[b*ND + j] = c;
        else       g_gi[b*ND + j - ND] = c;
    }
    lacc = warp_sum(lacc);
    if(lane==0){
        atomicAdd(&g_aux, BETA * lacc * (1.f/TD) * (1.f/NB));
        atomicAdd(&g_hist[it*NK + bi], 1);
    }
    if(do_addr){
        const float* lrow = g_alog + bi*65;
        float gate = 1.f/(1.f + expf(-lrow[64]));
        float ent = warp_sum(addr_finish(b, lrow[lane], lrow[lane+32], gate, lane));
        if(lane==0) atomicAdd(&g_aux, ent*(1.f/(float)NB));
    }
}

// ---------------- write output (+ fused codebook-usage entropy) --------------
__global__ void k_out(float* __restrict__ out, int out_n){
    int t0 = threadIdx.x;
    int t = blockIdx.x*256 + t0;
    int b = t >> 9, j = t & 511;
    out[t] = (j < ND) ? g_gr[b*ND + j] : g_gi[b*ND + j - ND];
    if(blockIdx.x == 0){
        __shared__ float s_red[8];
        float e = 0.f;
        for(int q=t0; q<NK; q+=256){
            #pragma unroll
            for(int it=0;it<5;it++){
                float pp = (float)g_hist[it*NK + q] * (1.f/NB);
                e += -pp * logf(pp + 1e-10f);
            }
        }
        e = warp_sum(e);
        if((t0&31)==0) s_red[t0>>5] = e;
        __syncthreads();
        if(t0==0){
            float v = 0.f;
            #pragma unroll
            for(int i=0;i<8;i++) v += s_red[i];
            if(out_n > NB*TD) out[out_n-1] = g_aux + v*(1.f/6.931471805599453f);
        }
    }
}

// =============================================================================
extern "C" void kernel_launch(void* const* d_in, const int* in_sizes, int n_in,
                              void* d_out, int out_size)
{
    const float* gw_real = (const float*)d_in[0];
    const float* gw_imag = (const float*)d_in[1];
    const float* mem_real= (const float*)d_in[2];
    const float* mem_imag= (const float*)d_in[3];
    const float* gate_w  = (const float*)d_in[4];
    const float* gate_b  = (const float*)d_in[5];
    const float* addr_w  = (const float*)d_in[6];
    const float* addr_b  = (const float*)d_in[7];
    const float* lnr_w   = (const float*)d_in[8];
    const float* lnr_b   = (const float*)d_in[9];
    const float* lni_w   = (const float*)d_in[10];
    const float* lni_b   = (const float*)d_in[11];
    const float* cln_s   = (const float*)d_in[12];
    const float* cln_b   = (const float*)d_in[13];
    const float* codebook= (const float*)d_in[14];
    float* out = (float*)d_out;

    const int SMEM_VQ = 2*VQ_STG;
    static int attr_done = 0;
    if(!attr_done){
        cudaFuncSetAttribute(k_vq, cudaFuncAttributeMaxDynamicSharedMemorySize, SMEM_VQ);
        attr_done = 1;
    }

    k_init  <<<128, 256>>>(codebook);
    k_logits<<<dim3(32,4), 256>>>(1, codebook, gw_real, gw_imag, addr_w, gate_w);
    k_logred<<<(NK*65+255)/256, 256>>>(1, addr_b, gate_b);
    k_logits<<<dim3(64,4), 256>>>(0, codebook, gw_real, gw_imag, addr_w, gate_w);
    k_logred<<<(NB*65+255)/256, 256>>>(0, addr_b, gate_b);
    k_addr_fin<<<256, 256>>>();

    for(int it=0; it<5; it++){
        k_mem <<<NB, 512>>>(mem_real, mem_imag, gw_real, gw_imag,
                            it==0 ? 1 : 0, it==4 ? 1 : 0,
                            lnr_w, lnr_b, lni_w, lni_b, cln_s, cln_b);
        k_vq  <<<dim3(16,16), 256, SMEM_VQ>>>();
        k_pick<<<256, 256>>>(codebook, it, it<4 ? 1 : 0);
    }
    k_out<<<4096, 256>>>(out, out_size);
}

// round 16
// speedup vs baseline: 1.6513x; 1.6513x over previous
#include <cuda_runtime.h>
#include <cuda_bf16.h>
#include <math.h>
#include <float.h>
#include <stdint.h>

#define NB 2048
#define ND 256
#define NS 64
#define NK 1024
#define TD 512          // 2*D
#define SD (NS*ND)      // 16384
#define KX 1536         // 3*TD for bf16x3
#define BETA 0.25f

// ---------------- device scratch ----------------
__device__ float g_mr[(size_t)NB*SD];
__device__ float g_mi[(size_t)NB*SD];
__device__ float g_gr[NB*ND];
__device__ float g_gi[NB*ND];
__device__ float g_zf[(size_t)NB*TD];
__device__ __nv_bfloat16 g_zb[(size_t)NB*KX];   // [zh | zh | zm]
__device__ __nv_bfloat16 g_cbb[(size_t)NK*KX];  // [ch | cm | ch]
__device__ float g_eff[NB*NS];
__device__ float g_ysq[NK];
__device__ float g_alog[NK*65];
__device__ float g_blog[NB*65];
__device__ float g_plog[4*NB*65];
__device__ float g_pscore[NB*16];
__device__ int   g_pidx[NB*16];
__device__ int   g_hist[5*NK];
__device__ float g_aux;

// ---------------- helpers ----------------
__device__ __forceinline__ float warp_sum(float v){
    #pragma unroll
    for(int o=16;o;o>>=1) v += __shfl_xor_sync(0xffffffffu, v, o);
    return v;
}
__device__ __forceinline__ void warp_sum2(float& a, float& b){
    #pragma unroll
    for(int o=16;o;o>>=1){
        a += __shfl_xor_sync(0xffffffffu, a, o);
        b += __shfl_xor_sync(0xffffffffu, b, o);
    }
}
__device__ __forceinline__ float warp_max(float v){
    #pragma unroll
    for(int o=16;o;o>>=1) v = fmaxf(v, __shfl_xor_sync(0xffffffffu, v, o));
    return v;
}
__device__ __forceinline__ float dot4(float4 a, float4 b){
    return a.x*b.x + a.y*b.y + a.z*b.z + a.w*b.w;
}
__device__ __forceinline__ void fma4(float4& acc, float s, float4 v){
    acc.x += s*v.x; acc.y += s*v.y; acc.z += s*v.z; acc.w += s*v.w;
}
__device__ __forceinline__ void scl4(float4& acc, float s){
    acc.x *= s; acc.y *= s; acc.z *= s; acc.w *= s;
}
__device__ __forceinline__ float4 mix4(float om, float4 a, float e, float4 g){
    float4 r; r.x=om*a.x+e*g.x; r.y=om*a.y+e*g.y; r.z=om*a.z+e*g.z; r.w=om*a.w+e*g.w; return r;
}
__device__ __forceinline__ float h4(float4 v){ return v.x+v.y+v.z+v.w; }
__device__ __forceinline__ float ss4(float4 v){
    return v.x*v.x + v.y*v.y + v.z*v.z + v.w*v.w;
}
__device__ __forceinline__ float4 lnorm4(float4 v, float mu, float inv, float4 w, float4 b){
    float4 r;
    r.x=(v.x-mu)*inv*w.x+b.x; r.y=(v.y-mu)*inv*w.y+b.y;
    r.z=(v.z-mu)*inv*w.z+b.z; r.w=(v.w-mu)*inv*w.w+b.w; return r;
}
__device__ __forceinline__ float4 zero4(){ float4 z; z.x=z.y=z.z=z.w=0.f; return z; }
__device__ __forceinline__ void cp16(void* dst, const void* src){
    unsigned u = (unsigned)__cvta_generic_to_shared(dst);
    asm volatile("cp.async.cg.shared.global [%0], [%1], 16;" :: "r"(u), "l"(src));
}
__device__ __forceinline__ void mma16(float* d, const unsigned* a, const unsigned* b){
    asm volatile("mma.sync.aligned.m16n8k16.row.col.f32.bf16.bf16.f32 "
        "{%0,%1,%2,%3},{%4,%5,%6,%7},{%8,%9},{%0,%1,%2,%3};"
        : "+f"(d[0]),"+f"(d[1]),"+f"(d[2]),"+f"(d[3])
        : "r"(a[0]),"r"(a[1]),"r"(a[2]),"r"(a[3]),"r"(b[0]),"r"(b[1]));
}

// ---------------- softmax/top3/eff (warp-collective, returns lane-partial ent)
__device__ __forceinline__ float addr_finish(int b, float v0, float v1, float gate, int lane){
    float m  = warp_max(fmaxf(v0,v1));
    float e0 = expf(v0-m), e1 = expf(v1-m);
    float ssum = warp_sum(e0+e1);
    float w0 = e0/ssum, w1 = e1/ssum;
    float ent = -(w0*logf(w0+1e-10f)) - (w1*logf(w1+1e-10f));
    float a0=w0, a1=w1; int i0=lane, i1=lane+32;
    float tv[3]; int ti[3];
    #pragma unroll
    for(int p3=0;p3<3;p3++){
        float v; int ix;
        if(a0>a1 || (a0==a1 && i0<i1)){ v=a0; ix=i0; } else { v=a1; ix=i1; }
        #pragma unroll
        for(int o=16;o;o>>=1){
            float ov = __shfl_xor_sync(0xffffffffu, v, o);
            int   oi = __shfl_xor_sync(0xffffffffu, ix, o);
            if(ov>v || (ov==v && oi<ix)){ v=ov; ix=oi; }
        }
        tv[p3]=v; ti[p3]=ix;
        if(i0==ix) a0 = -1.f;
        if(i1==ix) a1 = -1.f;
    }
    float norm = 1.f/(tv[0]+tv[1]+tv[2]+1e-6f);
    float o0=0.f, o1=0.f;
    #pragma unroll
    for(int p3=0;p3<3;p3++){
        if(lane==ti[p3])    o0 = tv[p3]*norm;
        if(lane+32==ti[p3]) o1 = tv[p3]*norm;
    }
    g_eff[b*NS+lane]    = gate*o0;
    g_eff[b*NS+lane+32] = gate*o1;
    return ent;
}

// ---------------- init: ysq, codebook bf16x3 split, zero hist/aux ------------
__global__ void k_init(const float* __restrict__ cb){
    int gt = blockIdx.x*256 + threadIdx.x;
    int w = gt >> 5, lane = gt & 31;
    const float* row = cb + (size_t)w*TD;
    float p = 0.f;
    for(int j=lane;j<TD;j+=32){
        float c = row[j];
        p += c*c;
        __nv_bfloat16 ch = __float2bfloat16_rn(c);
        __nv_bfloat16 cm = __float2bfloat16_rn(c - __bfloat162float(ch));
        size_t base = (size_t)w*KX;
        g_cbb[base + j]        = ch;
        g_cbb[base + 512 + j]  = cm;
        g_cbb[base + 1024 + j] = ch;
    }
    p = warp_sum(p);
    if(lane==0) g_ysq[w] = p;
    if(gt < 5*NK) g_hist[gt] = 0;
    if(gt == 0) g_aux = 0.f;
}

// ---------------- logits GEMM (split-K x4) ----------------------------------
__global__ void __launch_bounds__(256) k_logits(int mode, const float* __restrict__ cb,
                                                const float* __restrict__ gr_in,
                                                const float* __restrict__ gi_in,
                                                const float* __restrict__ aw,
                                                const float* __restrict__ gw){
    __shared__ float s_w[65*68];
    __shared__ float s_x[32*68];
    int t = threadIdx.x;
    int ml = t >> 3, ng = t & 7;
    int m0 = blockIdx.x*32;
    int kb = blockIdx.y*128;
    float acc[9];
    #pragma unroll
    for(int i=0;i<9;i++) acc[i]=0.f;

    #pragma unroll
    for(int ch=0; ch<2; ch++){
        int k0 = kb + ch*64;
        __syncthreads();
        for(int idx=t; idx<1040; idx+=256){
            int n = idx>>4, j4 = (idx&15)*4;
            float4 v = (n<64) ? *(const float4*)&aw[(size_t)n*TD + k0 + j4]
                              : *(const float4*)&gw[k0 + j4];
            *(float4*)&s_w[n*68+j4] = v;
        }
        #pragma unroll
        for(int l=0;l<2;l++){
            int idx = t + l*256;
            int mm = idx>>4, j4 = (idx&15)*4;
            int kg = k0 + j4;
            const float* src;
            if(mode) src = &cb[(size_t)(m0+mm)*TD + kg];
            else     src = (kg < 256) ? &gr_in[(m0+mm)*ND + kg] : &gi_in[(m0+mm)*ND + kg - 256];
            *(float4*)&s_x[mm*68+j4] = *(const float4*)src;
        }
        __syncthreads();
        #pragma unroll 4
        for(int j=0;j<64;j+=4){
            float4 xv = *(const float4*)&s_x[ml*68+j];
            #pragma unroll
            for(int i=0;i<8;i++){
                float4 wv = *(const float4*)&s_w[(ng+i*8)*68+j];
                acc[i] += dot4(xv, wv);
            }
            if(ng==0){
                float4 wv = *(const float4*)&s_w[64*68+j];
                acc[8] += dot4(xv, wv);
            }
        }
    }
    float* pp = g_plog + blockIdx.y*(NB*65);
    int m = m0 + ml;
    #pragma unroll
    for(int i=0;i<8;i++) pp[m*65 + ng + i*8] = acc[i];
    if(ng==0) pp[m*65 + 64] = acc[8];
}

// ---------------- logits reduce ----------------------------------------------
__global__ void k_logred(int mode, const float* __restrict__ ab, const float* __restrict__ gb){
    int idx = blockIdx.x*256 + threadIdx.x;
    int M = mode ? NK : NB;
    if(idx >= M*65) return;
    int n = idx - (idx/65)*65;
    float s = g_plog[idx] + g_plog[NB*65+idx] + g_plog[2*NB*65+idx] + g_plog[3*NB*65+idx];
    s += (n < 64) ? ab[n] : gb[0];
    if(mode) g_alog[idx] = s; else g_blog[idx] = s;
}

// ---------------- iter-0 address finisher ------------------------------------
__global__ void __launch_bounds__(256) k_addr_fin(){
    int t = threadIdx.x, wid = t>>5, lane = t&31;
    int b = blockIdx.x*8 + wid;
    const float* row = g_blog + b*65;
    float gate = 1.f/(1.f + expf(-row[64]));
    float ent = warp_sum(addr_finish(b, row[lane], row[lane+32], gate, lane));
    __shared__ float s_e[8];
    if(lane==0) s_e[wid] = ent;
    __syncthreads();
    if(t==0){
        float es = 0.f;
        #pragma unroll
        for(int i=0;i<8;i++) es += s_e[i];
        atomicAdd(&g_aux, es*(1.f/(float)NB));
    }
}

// ---- fused assoc-mem (single pass, online softmax) + complex layernorm ------
__global__ void __launch_bounds__(512,2) k_mem(const float* __restrict__ mr_in,
                                               const float* __restrict__ mi_in,
                                               const float* __restrict__ gr_in,
                                               const float* __restrict__ gi_in,
                                               int first, int last,
                                               const float* __restrict__ lnrw, const float* __restrict__ lnrb,
                                               const float* __restrict__ lniw, const float* __restrict__ lnib,
                                               const float* __restrict__ clns, const float* __restrict__ clnb)
{
    __shared__ float s_g[TD];
    __shared__ float s_eff[NS];
    __shared__ float s_part[16*TD];
    __shared__ float s_wm[16];
    __shared__ float s_ws[16];
    __shared__ float s_wscale[17];
    __shared__ float s_red2[16];
    __shared__ float s_scal[2];

    int b = blockIdx.x, t = threadIdx.x, wid = t>>5, lane = t&31;
    const float* mrs = first ? (mr_in + (size_t)b*SD) : (g_mr + (size_t)b*SD);
    const float* mis = first ? (mi_in + (size_t)b*SD) : (g_mi + (size_t)b*SD);

    if(t<ND) s_g[t] = first ? gr_in[b*ND+t] : g_gr[b*ND+t];
    else     s_g[t] = first ? gi_in[b*ND + (t-ND)] : g_gi[b*ND + (t-ND)];
    if(t<NS) s_eff[t] = g_eff[b*NS+t];
    __syncthreads();

    const float4* sg4 = (const float4*)s_g;
    float4 gg0 = sg4[lane], gg1 = sg4[lane+32];
    float4 hh0 = sg4[64+lane], hh1 = sg4[64+lane+32];

    float4 ar0=zero4(), ar1=zero4(), ai0=zero4(), ai1=zero4();
    float om_m = -FLT_MAX, om_s = 0.f;

    #pragma unroll
    for(int r=0;r<4;r++){
        int s = wid*4 + r;
        const float4* pr = (const float4*)(mrs + s*ND);
        const float4* pi = (const float4*)(mis + s*ND);
        float4 a0 = __ldcs(&pr[lane]), a1 = __ldcs(&pr[lane+32]);
        float4 c0 = __ldcs(&pi[lane]), c1 = __ldcs(&pi[lane+32]);

        float sim = warp_sum(dot4(a0,gg0) + dot4(a1,gg1) + dot4(c0,hh0) + dot4(c1,hh1));

        float mnew = fmaxf(om_m, sim);
        float scale = expf(om_m - mnew);
        float w = expf(sim - mnew);
        scl4(ar0, scale); scl4(ar1, scale); scl4(ai0, scale); scl4(ai1, scale);
        fma4(ar0, w, a0); fma4(ar1, w, a1);
        fma4(ai0, w, c0); fma4(ai1, w, c1);
        om_s = om_s*scale + w;
        om_m = mnew;

        if(!last){
            float e = s_eff[s], om = 1.f - e;
            {
                float4 v0 = mix4(om, a0, e, gg0), v1 = mix4(om, a1, e, gg1);
                float sv = h4(v0)+h4(v1), sq = ss4(v0)+ss4(v1);
                warp_sum2(sv, sq);
                float mu  = sv*(1.f/ND);
                float var = sq*(1.f/ND) - mu*mu;
                float inv = 1.f/sqrtf(var + 1e-6f);
                const float4* w4 = (const float4*)lnrw; const float4* b4 = (const float4*)lnrb;
                float4* dst = (float4*)(g_mr + (size_t)b*SD + s*ND);
                __stcs(&dst[lane],    lnorm4(v0, mu, inv, __ldg(&w4[lane]),    __ldg(&b4[lane])));
                __stcs(&dst[lane+32], lnorm4(v1, mu, inv, __ldg(&w4[lane+32]), __ldg(&b4[lane+32])));
            }
            {
                float4 v0 = mix4(om, c0, e, hh0), v1 = mix4(om, c1, e, hh1);
                float sv = h4(v0)+h4(v1), sq = ss4(v0)+ss4(v1);
                warp_sum2(sv, sq);
                float mu  = sv*(1.f/ND);
                float var = sq*(1.f/ND) - mu*mu;
                float inv = 1.f/sqrtf(var + 1e-6f);
                const float4* w4 = (const float4*)lniw; const float4* b4 = (const float4*)lnib;
                float4* dst = (float4*)(g_mi + (size_t)b*SD + s*ND);
                __stcs(&dst[lane],    lnorm4(v0, mu, inv, __ldg(&w4[lane]),    __ldg(&b4[lane])));
                __stcs(&dst[lane+32], lnorm4(v1, mu, inv, __ldg(&w4[lane+32]), __ldg(&b4[lane+32])));
            }
        }
    }

    {
        float4* sp4 = (float4*)&s_part[wid*TD];
        sp4[lane]    = ar0; sp4[lane+32]    = ar1;
        sp4[64+lane] = ai0; sp4[64+lane+32] = ai1;
        if(lane==0){ s_wm[wid] = om_m; s_ws[wid] = om_s; }
    }
    __syncthreads();

    if(wid==0 && lane==0){
        float M = -FLT_MAX;
        #pragma unroll
        for(int w=0;w<16;w++) M = fmaxf(M, s_wm[w]);
        float total = 0.f;
        #pragma unroll
        for(int w=0;w<16;w++){
            float sc = expf(s_wm[w] - M);
            s_wscale[w] = sc;
            total += s_ws[w]*sc;
        }
        s_wscale[16] = 1.f/total;
    }
    __syncthreads();

    float invt = s_wscale[16];
    float red = 0.f;
    #pragma unroll
    for(int w=0;w<16;w++) red += s_wscale[w]*s_part[w*TD + t];
    red *= invt;
    __syncthreads();
    s_part[t] = red;
    __syncthreads();

    float zr=0.f, zi=0.f, mag=0.f;
    if(t < ND){
        zr = s_g[t]    + s_part[t];
        zi = s_g[ND+t] + s_part[ND+t];
        mag = sqrtf(zr*zr + zi*zi + 1e-8f);
    }
    float p = warp_sum(mag);
    if(lane==0) s_red2[wid] = p;
    __syncthreads();
    if(t==0){
        float m2=0.f;
        #pragma unroll
        for(int i=0;i<8;i++) m2 += s_red2[i];
        s_scal[0] = m2*(1.f/ND);
    }
    __syncthreads();
    float mean = s_scal[0];
    float dv = (t<ND) ? (mag-mean)*(mag-mean) : 0.f;
    p = warp_sum(dv);
    if(lane==0) s_red2[wid] = p;
    __syncthreads();
    if(t==0){
        float v2=0.f;
        #pragma unroll
        for(int i=0;i<8;i++) v2 += s_red2[i];
        s_scal[1] = 1.f/sqrtf(v2*(1.f/(ND-1)) + 1e-4f);
    }
    __syncthreads();
    if(t < ND){
        float nm = (mag-mean)*s_scal[1]*__ldg(&clns[t]) + __ldg(&clnb[t]);
        float h2 = zr*zr + zi*zi;
        float c, s;
        if(h2 > 0.f){ float ih = 1.f/sqrtf(h2); c = zr*ih; s = zi*ih; }
        else { c = 1.f; s = 0.f; }
        float zrv = nm*c, ziv = nm*s;
        size_t zfb = (size_t)b*TD;
        g_zf[zfb + t]      = zrv;
        g_zf[zfb + ND + t] = ziv;
        size_t zbb = (size_t)b*KX;
        __nv_bfloat16 hr = __float2bfloat16_rn(zrv);
        __nv_bfloat16 mr2 = __float2bfloat16_rn(zrv - __bfloat162float(hr));
        g_zb[zbb + t]         = hr;
        g_zb[zbb + 512 + t]   = hr;
        g_zb[zbb + 1024 + t]  = mr2;
        __nv_bfloat16 hi = __float2bfloat16_rn(ziv);
        __nv_bfloat16 mi2 = __float2bfloat16_rn(ziv - __bfloat162float(hi));
        g_zb[zbb + ND + t]        = hi;
        g_zb[zbb + 512 + ND + t]  = hi;
        g_zb[zbb + 1024 + ND + t] = mi2;
    }
}

// ---------------- VQ: bf16 HMMA distance GEMM + argmin ----------------------
#define VQ_A_BYTES 18432
#define VQ_B_BYTES 9216
#define VQ_STG (VQ_A_BYTES+VQ_B_BYTES)
__global__ void __launch_bounds__(256,2) k_vq(){
    extern __shared__ char vsm[];
    int tid = threadIdx.x, lane = tid&31, wid = tid>>5;
    int g = lane>>2, tig = lane&3;
    int wm = wid>>1, wn = wid&1;
    int b0 = blockIdx.x*128, k0 = blockIdx.y*64;

    float acc[2][4][4];
    #pragma unroll
    for(int i=0;i<2;i++)
        #pragma unroll
        for(int j=0;j<4;j++){ acc[i][j][0]=0.f; acc[i][j][1]=0.f; acc[i][j][2]=0.f; acc[i][j][3]=0.f; }

    #define LOAD_CHUNK(ch, stage) do{ \
        _Pragma("unroll") \
        for(int i=0;i<6;i++){ \
            int q = tid + i*256; \
            if(q < 1024){ \
                int row = q>>3, seg = q&7; \
                cp16(vsm + (stage)*VQ_STG + row*144 + seg*16, \
                     &g_zb[(size_t)(b0+row)*KX + (ch)*64 + seg*8]); \
            } else { \
                int q2 = q-1024; int row = q2>>3, seg = q2&7; \
                cp16(vsm + (stage)*VQ_STG + VQ_A_BYTES + row*144 + seg*16, \
                     &g_cbb[(size_t)(k0+row)*KX + (ch)*64 + seg*8]); \
            } \
        } \
        asm volatile("cp.async.commit_group;"); \
    }while(0)

    LOAD_CHUNK(0, 0);

    for(int ch=0; ch<24; ch++){
        if(ch < 23){
            LOAD_CHUNK(ch+1, (ch+1)&1);
            asm volatile("cp.async.wait_group 1;");
        } else {
            asm volatile("cp.async.wait_group 0;");
        }
        __syncthreads();

        const char* As = vsm + (ch&1)*VQ_STG;
        const char* Bs = As + VQ_A_BYTES;

        #pragma unroll
        for(int kk=0;kk<4;kk++){
            unsigned a[2][4], bfr[4][2];
            #pragma unroll
            for(int m4=0;m4<2;m4++){
                int r = wm*32 + m4*16 + g;
                const char* p = As + r*144 + kk*32 + tig*4;
                a[m4][0] = *(const unsigned*)p;
                a[m4][1] = *(const unsigned*)(p + 8*144);
                a[m4][2] = *(const unsigned*)(p + 16);
                a[m4][3] = *(const unsigned*)(p + 8*144 + 16);
            }
            #pragma unroll
            for(int n4=0;n4<4;n4++){
                int c = wn*32 + n4*8 + g;
                const char* p = Bs + c*144 + kk*32 + tig*4;
                bfr[n4][0] = *(const unsigned*)p;
                bfr[n4][1] = *(const unsigned*)(p + 16);
            }
            #pragma unroll
            for(int m4=0;m4<2;m4++)
                #pragma unroll
                for(int n4=0;n4<4;n4++)
                    mma16(acc[m4][n4], a[m4], bfr[n4]);
        }
        __syncthreads();
    }

    float* s_val = (float*)vsm;
    int*   s_idx = (int*)(vsm + 1024);

    float ys[4][2];
    #pragma unroll
    for(int n4=0;n4<4;n4++){
        int c = k0 + wn*32 + n4*8 + tig*2;
        ys[n4][0] = __ldg(&g_ysq[c]);
        ys[n4][1] = __ldg(&g_ysq[c+1]);
    }

    #pragma unroll
    for(int m4=0;m4<2;m4++){
        float bvA = FLT_MAX, bvB = FLT_MAX; int biA = 0x7fffffff, biB = 0x7fffffff;
        #pragma unroll
        for(int n4=0;n4<4;n4++){
            int cb0 = k0 + wn*32 + n4*8 + tig*2;
            float d0 = ys[n4][0] - 2.f*acc[m4][n4][0];
            float d1 = ys[n4][1] - 2.f*acc[m4][n4][1];
            float d2 = ys[n4][0] - 2.f*acc[m4][n4][2];
            float d3 = ys[n4][1] - 2.f*acc[m4][n4][3];
            if(d0 < bvA || (d0==bvA && cb0   < biA)){ bvA = d0; biA = cb0;   }
            if(d1 < bvA || (d1==bvA && cb0+1 < biA)){ bvA = d1; biA = cb0+1; }
            if(d2 < bvB || (d2==bvB && cb0   < biB)){ bvB = d2; biB = cb0;   }
            if(d3 < bvB || (d3==bvB && cb0+1 < biB)){ bvB = d3; biB = cb0+1; }
        }
        #pragma unroll
        for(int o=1;o<4;o<<=1){
            float ovA = __shfl_xor_sync(0xffffffffu, bvA, o);
            int   oiA = __shfl_xor_sync(0xffffffffu, biA, o);
            if(ovA<bvA || (ovA==bvA && oiA<biA)){ bvA=ovA; biA=oiA; }
            float ovB = __shfl_xor_sync(0xffffffffu, bvB, o);
            int   oiB = __shfl_xor_sync(0xffffffffu, biB, o);
            if(ovB<bvB || (ovB==bvB && oiB<biB)){ bvB=ovB; biB=oiB; }
        }
        if(tig==0){
            int rA = wm*32 + m4*16 + g;
            s_val[rA*2+wn]     = bvA; s_idx[rA*2+wn]     = biA;
            s_val[(rA+8)*2+wn] = bvB; s_idx[(rA+8)*2+wn] = biB;
        }
    }
    __syncthreads();
    if(tid < 128){
        float bv = FLT_MAX; int bi = 0x7fffffff;
        #pragma unroll
        for(int j=0;j<2;j++){
            float v = s_val[tid*2+j]; int ix = s_idx[tid*2+j];
            if(v<bv || (v==bv && ix<bi)){ bv=v; bi=ix; }
        }
        g_pscore[(size_t)(b0+tid)*16 + blockIdx.y] = bv;
        g_pidx  [(size_t)(b0+tid)*16 + blockIdx.y] = bi;
    }
    #undef LOAD_CHUNK
}

// ------- final argmin, gather, loss, hist + fused next-iter address ----------
__global__ void __launch_bounds__(256) k_pick(const float* __restrict__ cb, int it, int do_addr){
    int wid = threadIdx.x>>5, lane = threadIdx.x&31;
    int b = blockIdx.x*8 + wid;
    float bv = FLT_MAX; int bi = 0x7fffffff;
    if(lane < 16){ bv = g_pscore[b*16+lane]; bi = g_pidx[b*16+lane]; }
    #pragma unroll
    for(int o=1;o<32;o<<=1){
        float ov = __shfl_xor_sync(0xffffffffu, bv, o);
        int   oi = __shfl_xor_sync(0xffffffffu, bi, o);
        if(ov<bv || (ov==bv && oi<bi)){ bv=ov; bi=oi; }
    }
    bi = __shfl_sync(0xffffffffu, bi, 0);
    const float* row = cb + (size_t)bi*TD;
    float lacc = 0.f;
    for(int j=lane;j<TD;j+=32){
        float c = row[j], z = g_zf[(size_t)b*TD + j];
        float df = c - z; lacc += df*df;
        if(j < ND) g_gr[b*ND + j] = c;
        else       g_gi[b*ND + j - ND] = c;
    }
    lacc = warp_sum(lacc);
    if(lane==0){
        atomicAdd(&g_aux, BETA * lacc * (1.f/TD) * (1.f/NB));
        atomicAdd(&g_hist[it*NK + bi], 1);
    }
    if(do_addr){
        const float* lrow = g_alog + bi*65;
        float gate = 1.f/(1.f + expf(-lrow[64]));
        float ent = warp_sum(addr_finish(b, lrow[lane], lrow[lane+32], gate, lane));
        if(lane==0) atomicAdd(&g_aux, ent*(1.f/(float)NB));
    }
}

// ---------------- write output (+ fused codebook-usage entropy) --------------
__global__ void k_out(float* __restrict__ out, int out_n){
    int t0 = threadIdx.x;
    int t = blockIdx.x*256 + t0;
    int b = t >> 9, j = t & 511;
    out[t] = (j < ND) ? g_gr[b*ND + j] : g_gi[b*ND + j - ND];
    if(blockIdx.x == 0){
        __shared__ float s_red[8];
        float e = 0.f;
        for(int q=t0; q<NK; q+=256){
            #pragma unroll
            for(int it=0;it<5;it++){
                float pp = (float)g_hist[it*NK + q] * (1.f/NB);
                e += -pp * logf(pp + 1e-10f);
            }
        }
        e = warp_sum(e);
        if((t0&31)==0) s_red[t0>>5] = e;
        __syncthreads();
        if(t0==0){
            float v = 0.f;
            #pragma unroll
            for(int i=0;i<8;i++) v += s_red[i];
            if(out_n > NB*TD) out[out_n-1] = g_aux + v*(1.f/6.931471805599453f);
        }
    }
}

// =============================================================================
extern "C" void kernel_launch(void* const* d_in, const int* in_sizes, int n_in,
                              void* d_out, int out_size)
{
    const float* gw_real = (const float*)d_in[0];
    const float* gw_imag = (const float*)d_in[1];
    const float* mem_real= (const float*)d_in[2];
    const float* mem_imag= (const float*)d_in[3];
    const float* gate_w  = (const float*)d_in[4];
    const float* gate_b  = (const float*)d_in[5];
    const float* addr_w  = (const float*)d_in[6];
    const float* addr_b  = (const float*)d_in[7];
    const float* lnr_w   = (const float*)d_in[8];
    const float* lnr_b   = (const float*)d_in[9];
    const float* lni_w   = (const float*)d_in[10];
    const float* lni_b   = (const float*)d_in[11];
    const float* cln_s   = (const float*)d_in[12];
    const float* cln_b   = (const float*)d_in[13];
    const float* codebook= (const float*)d_in[14];
    float* out = (float*)d_out;

    const int SMEM_VQ = 2*VQ_STG;
    static int attr_done = 0;
    if(!attr_done){
        cudaFuncSetAttribute(k_vq, cudaFuncAttributeMaxDynamicSharedMemorySize, SMEM_VQ);
        attr_done = 1;
    }

    k_init  <<<128, 256>>>(codebook);
    k_logits<<<dim3(32,4), 256>>>(1, codebook, gw_real, gw_imag, addr_w, gate_w);
    k_logred<<<(NK*65+255)/256, 256>>>(1, addr_b, gate_b);
    k_logits<<<dim3(64,4), 256>>>(0, codebook, gw_real, gw_imag, addr_w, gate_w);
    k_logred<<<(NB*65+255)/256, 256>>>(0, addr_b, gate_b);
    k_addr_fin<<<256, 256>>>();

    for(int it=0; it<5; it++){
        k_mem <<<NB, 512>>>(mem_real, mem_imag, gw_real, gw_imag,
                            it==0 ? 1 : 0, it==4 ? 1 : 0,
                            lnr_w, lnr_b, lni_w, lni_b, cln_s, cln_b);
        k_vq  <<<dim3(16,16), 256, SMEM_VQ>>>();
        k_pick<<<256, 256>>>(codebook, it, it<4 ? 1 : 0);
    }
    k_out<<<4096, 256>>>(out, out_size);
}